// round 1
// baseline (speedup 1.0000x reference)
#include <cuda_runtime.h>

#define HID 10
#define WSTRIDE 33              // padded wire stride (floats): bank = (w + d) mod 32
#define RS 2128                 // padded row stride (floats): 64*33 + 16 -> rows offset by 16 banks
#define WARPS_PER_BLOCK 8
#define THREADS 256
#define GRID 152

// Shared layout (floats): [0, 8*2*RS) per-warp row buffers, then A/B pair tables.
#define SMEM_FLOATS (WARPS_PER_BLOCK * 2 * RS)
#define SMEM_BYTES  (SMEM_FLOATS * 4 + 2 * 160 * 8)

__global__ __launch_bounds__(THREADS, 1)
void iin_kernel(const float* __restrict__ outputs,
                const int* __restrict__ tests32,
                const long long* __restrict__ tests64,
                const float* __restrict__ W1,
                const float* __restrict__ b1,
                const float* __restrict__ W2,
                float* __restrict__ out,
                int B)
{
    extern __shared__ float smem[];
    float* rowBuf = smem;
    unsigned long long* aPair = (unsigned long long*)(smem + SMEM_FLOATS); // W1[32+2t][j],W1[33+2t][j]
    unsigned long long* bPair = aPair + 160;                               // W1[2t][j],  W1[2t+1][j]

    const int tid  = threadIdx.x;
    const int lane = tid & 31;
    const int warp = tid >> 5;
    const int li   = lane & 15;   // lane within half-warp (handles wires li, li+16, li+32, li+48)
    const int half = lane >> 4;   // which of the warp's 2 rows

    // Build packed (even-d, odd-d) f32x2 weight tables in shared.
    for (int idx = tid; idx < 160; idx += THREADS) {
        int t = idx / HID, j = idx - t * HID;
        unsigned a0 = __float_as_uint(W1[(32 + 2 * t) * HID + j]);
        unsigned a1 = __float_as_uint(W1[(33 + 2 * t) * HID + j]);
        unsigned c0 = __float_as_uint(W1[(2 * t) * HID + j]);
        unsigned c1 = __float_as_uint(W1[(2 * t + 1) * HID + j]);
        aPair[idx] = ((unsigned long long)a1 << 32) | a0;
        bPair[idx] = ((unsigned long long)c1 << 32) | c0;
    }
    __syncthreads();

    float w2r[HID], b1r[HID];
#pragma unroll
    for (int j = 0; j < HID; ++j) { w2r[j] = W2[j]; b1r[j] = b1[j]; }

    // Runtime dtype detection for `tests`: if stored as int64, every odd int32
    // word is a zero high-half (values < 64). Probe 32 odd words: P(false hit) ~ 64^-32.
    int pidx = 2 * lane + 1;
    if (pidx > 2 * B - 1) pidx = 2 * B - 1;
    int probe = tests32[pidx];
    const bool idx32 = __any_sync(0xffffffffu, probe != 0);

    float* myBuf = rowBuf + warp * (2 * RS);
    const float* rb = myBuf + half * RS;   // this lane's row slice

    // Precompute per-wire shared pointers (conflict-free stride-33 layout).
    const float* wp[4];
#pragma unroll
    for (int c = 0; c < 4; ++c) wp[c] = rb + (li + 16 * c) * WSTRIDE;

    const int nPairs  = B >> 1;
    const int gw      = blockIdx.x * WARPS_PER_BLOCK + warp;
    const int gstride = gridDim.x * WARPS_PER_BLOCK;

    for (int p = gw; p < nPairs; p += gstride) {
        // ---------- load 2 rows, coalesced LDG.128, scalar STS into padded layout ----------
        __syncwarp();
#pragma unroll
        for (int rr = 0; rr < 2; ++rr) {
            const float4* g = (const float4*)(outputs + (size_t)(2 * p + rr) * 2048);
            float* dst = myBuf + rr * RS;
#pragma unroll
            for (int k = 0; k < 16; ++k) {
                int c = lane + 32 * k;          // global float4-chunk within row
                float4 v = g[c];
                float* d4 = dst + (c >> 3) * WSTRIDE + ((c & 7) << 2);
                d4[0] = v.x; d4[1] = v.y; d4[2] = v.z; d4[3] = v.w;
            }
        }
        __syncwarp();

        // ---------- main loop: q[w][j] = sum_d wire[w][d] * W1[32+d][j], f32x2 over (2t, 2t+1) ----------
        unsigned long long acc[4][HID];
#pragma unroll
        for (int c = 0; c < 4; ++c)
#pragma unroll
            for (int j = 0; j < HID; ++j) acc[c][j] = 0ULL;

#pragma unroll
        for (int t = 0; t < 16; ++t) {
            unsigned long long a2[HID];
#pragma unroll
            for (int jj = 0; jj < HID; jj += 2) {        // broadcast LDS.128
                ulonglong2 v = *(const ulonglong2*)(aPair + t * HID + jj);
                a2[jj] = v.x; a2[jj + 1] = v.y;
            }
#pragma unroll
            for (int c = 0; c < 4; ++c) {
                float xlo = wp[c][2 * t];
                float xhi = wp[c][2 * t + 1];
                unsigned long long x2;
                asm("mov.b64 %0, {%1,%2};" : "=l"(x2) : "f"(xlo), "f"(xhi));
#pragma unroll
                for (int j = 0; j < HID; ++j)
                    asm("fma.rn.f32x2 %0, %1, %2, %0;"
                        : "+l"(acc[c][j]) : "l"(x2), "l"(a2[j]));
            }
        }

        // ---------- per-row person/location ----------
        const int row = 2 * p + half;
        int person, loc;
        if (idx32) { person = tests32[2 * row];       loc = tests32[2 * row + 1]; }
        else       { person = (int)tests64[2 * row];  loc = (int)tests64[2 * row + 1]; }

        // ---------- pA[j] = person_vec . W1[0:32][j] : 16 lanes, one d-pair each, butterfly all-reduce ----------
        const float* pvp = rb + person * WSTRIDE;
        float plo = pvp[2 * li], phi = pvp[2 * li + 1];
        unsigned long long xp;
        asm("mov.b64 %0, {%1,%2};" : "=l"(xp) : "f"(plo), "f"(phi));
        float pb[HID];
#pragma unroll
        for (int j = 0; j < HID; ++j) {
            unsigned long long pr;
            asm("mul.rn.f32x2 %0, %1, %2;" : "=l"(pr) : "l"(xp), "l"(bPair[li * HID + j]));
            pb[j] = __uint_as_float((unsigned)pr) + __uint_as_float((unsigned)(pr >> 32));
        }
#pragma unroll
        for (int off = 8; off; off >>= 1)
#pragma unroll
            for (int j = 0; j < HID; ++j)
                pb[j] += __shfl_xor_sync(0xffffffffu, pb[j], off);
#pragma unroll
        for (int j = 0; j < HID; ++j) pb[j] += b1r[j];

        // ---------- logits (b2 cancels in lse - logit) ----------
        float lg[4];
#pragma unroll
        for (int c = 0; c < 4; ++c) {
            float s = 0.f;
#pragma unroll
            for (int j = 0; j < HID; ++j) {
                float q = __uint_as_float((unsigned)acc[c][j]) +
                          __uint_as_float((unsigned)(acc[c][j] >> 32)) + pb[j];
                q = fmaxf(q, 0.f);
                s = fmaf(q, w2r[j], s);
            }
            lg[c] = s;
        }

        // ---------- log-softmax over 64 wires (16-lane butterfly) ----------
        float m = fmaxf(fmaxf(lg[0], lg[1]), fmaxf(lg[2], lg[3]));
#pragma unroll
        for (int off = 8; off; off >>= 1)
            m = fmaxf(m, __shfl_xor_sync(0xffffffffu, m, off));
        float s = __expf(lg[0] - m) + __expf(lg[1] - m) + __expf(lg[2] - m) + __expf(lg[3] - m);
#pragma unroll
        for (int off = 8; off; off >>= 1)
            s += __shfl_xor_sync(0xffffffffu, s, off);
        float lse = m + __logf(s);

        int slot = loc >> 4;
        float sel = (slot == 0) ? lg[0] : (slot == 1) ? lg[1] : (slot == 2) ? lg[2] : lg[3];
        float lv = __shfl_sync(0xffffffffu, sel, (half << 4) | (loc & 15));
        if (li == 0) out[row] = lse - lv;
        __syncwarp();
    }
}

extern "C" void kernel_launch(void* const* d_in, const int* in_sizes, int n_in,
                              void* d_out, int out_size)
{
    const float*     outputs = (const float*)d_in[0];
    const void*      tests   = d_in[1];
    const float*     W1      = (const float*)d_in[2];
    const float*     b1      = (const float*)d_in[3];
    const float*     W2      = (const float*)d_in[4];
    float*           out     = (float*)d_out;

    int B = in_sizes[0] / 2048;   // 8192

    cudaFuncSetAttribute(iin_kernel, cudaFuncAttributeMaxDynamicSharedMemorySize, SMEM_BYTES);

    iin_kernel<<<GRID, THREADS, SMEM_BYTES>>>(
        outputs, (const int*)tests, (const long long*)tests, W1, b1, W2, out, B);
}

// round 4
// speedup vs baseline: 1.0372x; 1.0372x over previous
#include <cuda_runtime.h>

#define HID 10
#define WARPS 12
#define THREADS (WARPS * 32)
#define ROWF 2048                      // floats per row

// Shared layout (floats):
//   [0, WARPS*2*ROWF)  per-warp double row buffers (XOR-swizzled 16B chunks)
//   aQ: 8 quad-blocks x 20 ull  (W1 wire-half, d=32..63), 16B aligned
//   bQ: 8 groups x 22 ull (stride-padded, W1 person-half, d=0..31)
#define ROWAREA   (WARPS * 2 * ROWF)
#define AQ_OFF    ROWAREA              // 160 ull = 320 floats
#define BQ_OFF    (ROWAREA + 320)      // 176 ull = 352 floats
#define SMEM_FLOATS (ROWAREA + 320 + 352)
#define SMEM_BYTES  (SMEM_FLOATS * 4)

typedef unsigned long long ull;

__device__ __forceinline__ void fma2(ull& acc, ull a, ull b) {
    asm("fma.rn.f32x2 %0, %1, %2, %0;" : "+l"(acc) : "l"(a), "l"(b));
}
__device__ __forceinline__ float2 unp(ull v) {
    float2 r; asm("mov.b64 {%0,%1}, %2;" : "=f"(r.x), "=f"(r.y) : "l"(v)); return r;
}
__device__ __forceinline__ unsigned swchunk(unsigned w, unsigned k) {
    return 8u * w + (k ^ (w & 7u));    // 16B-chunk slot within a row buffer
}
__device__ __forceinline__ void cpa16(unsigned dst, const void* src) {
    asm volatile("cp.async.cg.shared.global [%0], [%1], 16;" :: "r"(dst), "l"(src));
}
__device__ __forceinline__ void cpa_commit() {
    asm volatile("cp.async.commit_group;");
}

__global__ __launch_bounds__(THREADS, 1)
void iin_kernel(const float* __restrict__ outputs,
                const int* __restrict__ tests32,
                const long long* __restrict__ tests64,
                const float* __restrict__ W1,
                const float* __restrict__ b1,
                const float* __restrict__ W2,
                float* __restrict__ out,
                int B)
{
    extern __shared__ float smem[];
    const int tid  = threadIdx.x;
    const int lane = tid & 31;
    const int warp = tid >> 5;

    // ---- build weight tables (16B-aligned double2 blocks) ----
    ull* aQ = (ull*)(smem + AQ_OFF);   // [t2][sub(2)][j(10)]  d = 32 + 4*t2 + 2*sub
    ull* bQ = (ull*)(smem + BQ_OFF);   // [q]*22 + sub*10 + j  d = 4*q + 2*sub
    for (int idx = tid; idx < 160; idx += THREADS) {
        int t2 = idx / 20, r = idx % 20, sub = r / 10, j = r % 10;
        int d0 = 32 + 4 * t2 + 2 * sub;
        unsigned lo = __float_as_uint(W1[d0 * HID + j]);
        unsigned hi = __float_as_uint(W1[(d0 + 1) * HID + j]);
        aQ[t2 * 20 + sub * 10 + j] = ((ull)hi << 32) | lo;
        int e0 = 4 * t2 + 2 * sub;   // reuse t2 as q for the B table
        unsigned blo = __float_as_uint(W1[e0 * HID + j]);
        unsigned bhi = __float_as_uint(W1[(e0 + 1) * HID + j]);
        bQ[t2 * 22 + sub * 10 + j] = ((ull)bhi << 32) | blo;
    }
    __syncthreads();

    float w2r[HID], b1r[HID];
#pragma unroll
    for (int j = 0; j < HID; ++j) { w2r[j] = W2[j]; b1r[j] = b1[j]; }

    // tests dtype probe (int64 -> every odd int32 word is a zero high-half)
    int pidx = 2 * lane + 1; if (pidx > 2 * B - 1) pidx = 2 * B - 1;
    const bool idx32 = __any_sync(0xffffffffu, tests32[pidx] != 0);

    // per-warp double buffers
    float* buf0 = smem + warp * 2 * ROWF;
    float* buf1 = buf0 + ROWF;
    unsigned sbase;
    asm("{ .reg .u64 t; cvta.to.shared.u64 t, %1; cvt.u32.u64 %0, t; }"
        : "=r"(sbase) : "l"(buf0));
    unsigned sb[2] = { sbase, sbase + ROWF * 4u };
    float* bufp[2] = { buf0, buf1 };

    const int gw      = blockIdx.x * WARPS + warp;
    const int gstride = gridDim.x * WARPS;

    // lane copies chunks c = lane + 32u, u = 0..15 (coalesced 16B; 512 chunks = full row)
    unsigned dsto[16];
#pragma unroll
    for (int u = 0; u < 16; ++u) {
        unsigned c = lane + 32u * u, w = c >> 3, k = c & 7;
        dsto[u] = swchunk(w, k) * 16u;
    }

    const ull* aT = aQ;
    const double2* bp2 = (const double2*)(bQ + (lane & 7) * 22);

    int cur = 0;
    int r0 = gw;
    if (r0 < B) {
        const char* src = (const char*)(outputs + (size_t)r0 * ROWF) + (size_t)lane * 16u;
#pragma unroll
        for (int u = 0; u < 16; ++u) cpa16(sb[0] + dsto[u], src + 512u * u);
        cpa_commit();
    }

    for (int row = r0; row < B; row += gstride) {
        int nxt = row + gstride;
        bool pf = nxt < B;
        if (pf) {
            const char* src = (const char*)(outputs + (size_t)nxt * ROWF) + (size_t)lane * 16u;
#pragma unroll
            for (int u = 0; u < 16; ++u) cpa16(sb[cur ^ 1] + dsto[u], src + 512u * u);
            cpa_commit();
            asm volatile("cp.async.wait_group 1;");
        } else {
            asm volatile("cp.async.wait_group 0;");
        }
        __syncwarp();

        const float* rb = bufp[cur];
        const double2* rp = (const double2*)rb;

        // ---- main loop: 2 wires/lane (w0=lane, w1=lane+32), f32x2 over d ----
        ull a0[HID], a1[HID];
#pragma unroll
        for (int j = 0; j < HID; ++j) { a0[j] = 0ULL; a1[j] = 0ULL; }

        const unsigned w0 = lane, w1 = lane + 32;
#pragma unroll
        for (int t2 = 0; t2 < 8; ++t2) {
            double2 xa = rp[swchunk(w0, t2)];
            double2 xb = rp[swchunk(w1, t2)];
            ull xa01 = __double_as_longlong(xa.x), xa23 = __double_as_longlong(xa.y);
            ull xb01 = __double_as_longlong(xb.x), xb23 = __double_as_longlong(xb.y);
            const double2* ap = (const double2*)(aT + t2 * 20);
#pragma unroll
            for (int jj = 0; jj < 5; ++jj) {
                double2 A0 = ap[jj];       // pair (d0,d0+1), j = 2jj, 2jj+1
                double2 A1 = ap[jj + 5];   // pair (d0+2,d0+3)
                ull A0x = __double_as_longlong(A0.x), A0y = __double_as_longlong(A0.y);
                ull A1x = __double_as_longlong(A1.x), A1y = __double_as_longlong(A1.y);
                fma2(a0[2 * jj],     xa01, A0x); fma2(a0[2 * jj + 1], xa01, A0y);
                fma2(a0[2 * jj],     xa23, A1x); fma2(a0[2 * jj + 1], xa23, A1y);
                fma2(a1[2 * jj],     xb01, A0x); fma2(a1[2 * jj + 1], xb01, A0y);
                fma2(a1[2 * jj],     xb23, A1x); fma2(a1[2 * jj + 1], xb23, A1y);
            }
        }

        // ---- person / location ----
        int person, loc;
        if (idx32) { person = tests32[2 * row];      loc = tests32[2 * row + 1]; }
        else       { person = (int)tests64[2 * row]; loc = (int)tests64[2 * row + 1]; }

        // ---- pA: person_vec . W1[0:32]  (8-lane groups, duplicated x4) ----
        unsigned q = lane & 7;
        double2 xp = rp[8u * (unsigned)person + (q ^ ((unsigned)person & 7u))];
        ull xp01 = __double_as_longlong(xp.x), xp23 = __double_as_longlong(xp.y);
        ull s2[HID];
#pragma unroll
        for (int j = 0; j < HID; ++j) s2[j] = 0ULL;
#pragma unroll
        for (int jj = 0; jj < 5; ++jj) {
            double2 B0 = bp2[jj], B1 = bp2[jj + 5];
            fma2(s2[2 * jj],     xp01, __double_as_longlong(B0.x));
            fma2(s2[2 * jj + 1], xp01, __double_as_longlong(B0.y));
            fma2(s2[2 * jj],     xp23, __double_as_longlong(B1.x));
            fma2(s2[2 * jj + 1], xp23, __double_as_longlong(B1.y));
        }
        float pb[HID];
#pragma unroll
        for (int j = 0; j < HID; ++j) { float2 f = unp(s2[j]); pb[j] = f.x + f.y; }
#pragma unroll
        for (int off = 4; off; off >>= 1)
#pragma unroll
            for (int j = 0; j < HID; ++j)
                pb[j] += __shfl_xor_sync(0xffffffffu, pb[j], off);
#pragma unroll
        for (int j = 0; j < HID; ++j) pb[j] += b1r[j];

        // ---- logits (b2 cancels in lse - logit) ----
        float lg0 = 0.f, lg1 = 0.f;
#pragma unroll
        for (int j = 0; j < HID; ++j) {
            float2 f0 = unp(a0[j]), f1 = unp(a1[j]);
            float q0 = fmaxf(f0.x + f0.y + pb[j], 0.f);
            float q1 = fmaxf(f1.x + f1.y + pb[j], 0.f);
            lg0 = fmaf(q0, w2r[j], lg0);
            lg1 = fmaf(q1, w2r[j], lg1);
        }

        // ---- log-softmax over 64 wires (full-warp butterfly) ----
        float m = fmaxf(lg0, lg1);
#pragma unroll
        for (int off = 16; off; off >>= 1)
            m = fmaxf(m, __shfl_xor_sync(0xffffffffu, m, off));
        float s = __expf(lg0 - m) + __expf(lg1 - m);
#pragma unroll
        for (int off = 16; off; off >>= 1)
            s += __shfl_xor_sync(0xffffffffu, s, off);
        float lse = m + __logf(s);

        float sel = (loc >= 32) ? lg1 : lg0;
        float lv  = __shfl_sync(0xffffffffu, sel, loc & 31);
        if (lane == 0) out[row] = lse - lv;

        __syncwarp();         // protect buf[cur] before next iteration's prefetch
        cur ^= 1;
    }
}

extern "C" void kernel_launch(void* const* d_in, const int* in_sizes, int n_in,
                              void* d_out, int out_size)
{
    const float* outputs = (const float*)d_in[0];
    const void*  tests   = d_in[1];
    const float* W1      = (const float*)d_in[2];
    const float* b1      = (const float*)d_in[3];
    const float* W2      = (const float*)d_in[4];
    float*       out     = (float*)d_out;

    int B = in_sizes[0] / ROWF;   // 8192

    int grid = 0;
    cudaDeviceGetAttribute(&grid, cudaDevAttrMultiProcessorCount, 0);
    if (grid <= 0) grid = 148;
    cudaFuncSetAttribute(iin_kernel, cudaFuncAttributeMaxDynamicSharedMemorySize, SMEM_BYTES);

    iin_kernel<<<grid, THREADS, SMEM_BYTES>>>(
        outputs, (const int*)tests, (const long long*)tests, W1, b1, W2, out, B);
}